// round 7
// baseline (speedup 1.0000x reference)
#include <cuda_runtime.h>
#include <math.h>

#define Bdim 64
#define Sdim 1024
#define Idim 1024
#define Hdim 1024
#define NB_REC 128
#define REC_THREADS 512

// Scratch (allocation-free rule: __device__ globals)
__device__ float g_hbuf[2][Bdim * Hdim];
__device__ unsigned g_cnt;
__device__ unsigned g_flag;

typedef unsigned long long ull;

// ---------------------------------------------------------------------------
__device__ __forceinline__ void fma2(ull& c, ull a, ull b) {
    asm("fma.rn.f32x2 %0, %1, %2, %0;" : "+l"(c) : "l"(a), "l"(b));
}
__device__ __forceinline__ float f2sum(ull v) {
    float2 f = *reinterpret_cast<float2*>(&v);
    return f.x + f.y;
}
__device__ __forceinline__ void cp16(void* d, const void* s) {
    unsigned sd = (unsigned)__cvta_generic_to_shared(d);
    asm volatile("cp.async.cg.shared.global [%0], [%1], 16;" :: "r"(sd), "l"(s));
}
#define CP_COMMIT() asm volatile("cp.async.commit_group;")
#define CP_WAIT(n) asm volatile("cp.async.wait_group %0;" :: "n"(n))

// bulk async copy global->shared, completion via mbarrier tx-count
__device__ __forceinline__ void bulk_g2s(unsigned dst, const void* src,
                                         unsigned bytes, unsigned mbar) {
    asm volatile(
        "cp.async.bulk.shared::cluster.global.mbarrier::complete_tx::bytes "
        "[%0], [%1], %2, [%3];"
        :: "r"(dst), "l"(src), "r"(bytes), "r"(mbar) : "memory");
}
__device__ __forceinline__ void mbar_init(unsigned mbar, unsigned cnt) {
    asm volatile("mbarrier.init.shared.b64 [%0], %1;" :: "r"(mbar), "r"(cnt)
                 : "memory");
}
__device__ __forceinline__ void mbar_expect_tx(unsigned mbar, unsigned tx) {
    asm volatile("mbarrier.arrive.expect_tx.shared.b64 _, [%0], %1;"
                 :: "r"(mbar), "r"(tx) : "memory");
}
__device__ __forceinline__ void mbar_wait(unsigned mbar, unsigned parity) {
    asm volatile(
        "{\n\t"
        ".reg .pred P1;\n\t"
        "WAIT_LOOP_%=:\n\t"
        "mbarrier.try_wait.parity.acquire.cta.shared::cta.b64 P1, [%0], %1, 0x989680;\n\t"
        "@P1 bra.uni WAIT_DONE_%=;\n\t"
        "bra.uni WAIT_LOOP_%=;\n\t"
        "WAIT_DONE_%=:\n\t"
        "}"
        :: "r"(mbar), "r"(parity) : "memory");
}
__device__ __forceinline__ unsigned atom_add_release(unsigned* p, unsigned v) {
    unsigned old;
    asm volatile("atom.add.release.gpu.u32 %0, [%1], %2;"
                 : "=r"(old) : "l"(p), "r"(v) : "memory");
    return old;
}
__device__ __forceinline__ void st_release(unsigned* p, unsigned v) {
    asm volatile("st.release.gpu.u32 [%0], %1;" :: "l"(p), "r"(v) : "memory");
}
__device__ __forceinline__ unsigned ld_acquire(const unsigned* p) {
    unsigned v;
    asm volatile("ld.acquire.gpu.u32 %0, [%1];" : "=r"(v) : "l"(p) : "memory");
    return v;
}

// ---------------------------------------------------------------------------
__global__ void reset_state() {
    if (threadIdx.x == 0) {
        g_cnt = 0;
        g_flag = 0;
    }
}

__global__ void copy_h(const float* __restrict__ hin) {
    int i = blockIdx.x * blockDim.x + threadIdx.x;
    for (; i < Bdim * Hdim; i += gridDim.x * blockDim.x) g_hbuf[0][i] = hin[i];
}

// ---------------------------------------------------------------------------
// Phase 1: wx = X @ Wih^T + b  (unchanged from R4/R6 — measured good)
// ---------------------------------------------------------------------------
__global__ __launch_bounds__(256) void wx_gemm(const float* __restrict__ X,
                                               const float* __restrict__ W,
                                               const float* __restrict__ bias,
                                               float* __restrict__ out) {
    __shared__ float As[2][128 * 20];
    __shared__ float Ws[2][64 * 20];
    const int tid = threadIdx.x;
    const int tm = tid >> 4, tn = tid & 15;
    const long mBase = (long)blockIdx.y * 128;
    const int nBase = blockIdx.x * 64;

    const int xr = tid >> 1, xq = (tid & 1) * 8;
    const float* xg = X + (mBase + xr) * Idim + xq;
    const int wr = tid >> 2, wq = (tid & 3) * 4;
    const float* wg = W + (nBase + wr) * Idim + wq;

    ull acc[8][4];
#pragma unroll
    for (int i = 0; i < 8; i++)
#pragma unroll
        for (int j = 0; j < 4; j++) acc[i][j] = 0ull;

    cp16(&As[0][xr * 20 + xq], xg);
    cp16(&As[0][xr * 20 + xq + 4], xg + 4);
    cp16(&Ws[0][wr * 20 + wq], wg);
    CP_COMMIT();

    int buf = 0;
    for (int kt = 0; kt < Idim / 16; kt++) {
        if (kt + 1 < Idim / 16) {
            const int k0 = (kt + 1) * 16;
            cp16(&As[buf ^ 1][xr * 20 + xq], xg + k0);
            cp16(&As[buf ^ 1][xr * 20 + xq + 4], xg + k0 + 4);
            cp16(&Ws[buf ^ 1][wr * 20 + wq], wg + k0);
        }
        CP_COMMIT();
        CP_WAIT(1);
        __syncthreads();

        const float* A = &As[buf][tm * 8 * 20];
        const float* Bp = &Ws[buf][tn * 20];
#pragma unroll
        for (int q = 0; q < 4; q++) {
            ulonglong2 bt[4];
#pragma unroll
            for (int j = 0; j < 4; j++)
                bt[j] = *reinterpret_cast<const ulonglong2*>(&Bp[j * 320 + q * 4]);
#pragma unroll
            for (int i = 0; i < 8; i++) {
                ulonglong2 at =
                    *reinterpret_cast<const ulonglong2*>(&A[i * 20 + q * 4]);
#pragma unroll
                for (int j = 0; j < 4; j++) fma2(acc[i][j], at.x, bt[j].x);
#pragma unroll
                for (int j = 0; j < 4; j++) fma2(acc[i][j], at.y, bt[j].y);
            }
        }
        __syncthreads();
        buf ^= 1;
    }

#pragma unroll
    for (int j = 0; j < 4; j++) {
        float bv = bias[nBase + tn + 16 * j];
#pragma unroll
        for (int i = 0; i < 8; i++) {
            out[(mBase + tm * 8 + i) * Hdim + nBase + tn + 16 * j] =
                f2sum(acc[i][j]) + bv;
        }
    }
}

// ---------------------------------------------------------------------------
// Phase 2: persistent recurrence. 128 CTAs x 512 threads, 1 CTA/SM.
// CTA = 32 cols x 16 batches, Whh slice (32x1024) resident in smem.
// 16 warps = k-slices of 64; lane = (cpos:8, bpos:2, kpos:2):
//   thread tile 4 cols x 8 batches over 32 k  -> per 2k: 12 LDS.64 + 32 fma2
//   (crossbar/FMA ratio 1.5 vs 2.0 of the old 4x4 tile: -25% crossbar).
// k-halves merged via shfl.bfly(16); 16-warp partials reduced through sRed.
// Staging via cp.async.bulk + mbarrier; grid sync via release-atomic barrier.
// ---------------------------------------------------------------------------
__global__ __launch_bounds__(REC_THREADS, 1)
void rnn_recur(const float* __restrict__ Whh, const float* __restrict__ bhh,
               float* __restrict__ y, float* __restrict__ hlast) {
    extern __shared__ float sm[];
    float* sW = sm;                  // 32 x 1028
    float* sH = sm + 32 * 1028;      // 16 x 1028
    float* sRed = sH;                // overlay: 16 x 640 (after all sH reads)
    __shared__ unsigned long long mbar_storage;

    const int tid = threadIdx.x;
    const int bid = blockIdx.x;
    const int colBase = (bid & 31) * 32;
    const int batchBase = (bid >> 5) * 16;
    const unsigned mbar = (unsigned)__cvta_generic_to_shared(&mbar_storage);
    const unsigned sH_smem = (unsigned)__cvta_generic_to_shared(sH);

    if (tid == 0) mbar_init(mbar, 1);

    // cache Whh slice once: 32 rows x 1024 cols
#pragma unroll
    for (int i = 0; i < 16; i++) {
        int chunk = tid + i * REC_THREADS;
        int r = chunk >> 8, off = (chunk & 255) * 4;
        *reinterpret_cast<float4*>(&sW[r * 1028 + off]) =
            *reinterpret_cast<const float4*>(&Whh[(colBase + r) * Hdim + off]);
    }
    __syncthreads();  // mbar init + sW visible

    const int wid = tid >> 5, lane = tid & 31;
    const int cpos = lane & 7;               // cols cpos + 8*ci, ci<4
    const int bpos8 = ((lane >> 3) & 1) * 8; // batches bpos8 + bi, bi<8
    const int kpos = lane >> 4;              // k-half of warp slice
    const int kBase = wid * 64 + kpos * 32;
    const int bsel = kpos * 4;               // which 4 batches this lane stores

    const int ob = tid >> 5;  // batch 0..15
    const int oc = tid & 31;  // col 0..31
    const float bv = bhh[colBase + oc];
    const long ybase = (((long)(batchBase + ob)) << 20) + colBase + oc;
    const int hoff = ((batchBase + ob) << 10) + colBase + oc;
    const int rbase = ob * 40 + oc;
    float hv = 0.f;

    for (int s = 0; s < Sdim; s++) {
        const int p = s & 1;
        // stage h slice: 16 bulk copies of one 4KB row each
        if (tid == 0) {
            asm volatile("fence.proxy.async.shared::cta;" ::: "memory");
            mbar_expect_tx(mbar, 16 * 4096);
            const float* hsrc = g_hbuf[p] + ((long)batchBase << 10);
#pragma unroll
            for (int r = 0; r < 16; r++) {
                bulk_g2s(sH_smem + (unsigned)(r * 1028 * 4), hsrc + (r << 10),
                         4096, mbar);
            }
        }
        float wxv = __ldg(&y[ybase + ((long)s << 10)]);  // overlap with copy
        mbar_wait(mbar, (unsigned)p);

        ull acc[4][8];
#pragma unroll
        for (int ci = 0; ci < 4; ci++)
#pragma unroll
            for (int bi = 0; bi < 8; bi++) acc[ci][bi] = 0ull;

#pragma unroll 4
        for (int t = 0; t < 16; t++) {
            const int k = kBase + t * 2;
            ull wf[4], hf[8];
#pragma unroll
            for (int ci = 0; ci < 4; ci++)
                wf[ci] = *reinterpret_cast<const ull*>(
                    &sW[(cpos + 8 * ci) * 1028 + k]);
#pragma unroll
            for (int bi = 0; bi < 8; bi++)
                hf[bi] = *reinterpret_cast<const ull*>(
                    &sH[(bpos8 + bi) * 1028 + k]);
#pragma unroll
            for (int ci = 0; ci < 4; ci++)
#pragma unroll
                for (int bi = 0; bi < 8; bi++) fma2(acc[ci][bi], hf[bi], wf[ci]);
        }

        // merge the two k-halves of this warp: butterfly over kpos bit
        float part[4][8];
#pragma unroll
        for (int ci = 0; ci < 4; ci++)
#pragma unroll
            for (int bi = 0; bi < 8; bi++) {
                float v = f2sum(acc[ci][bi]);
                part[ci][bi] = v + __shfl_xor_sync(0xffffffffu, v, 16);
            }

        __syncthreads();  // all sH reads done before sRed overlay writes

        // each lane stores 4 of its 8 batches (kpos selects which half)
#pragma unroll
        for (int ci = 0; ci < 4; ci++)
#pragma unroll
            for (int j = 0; j < 4; j++) {
                int b = bpos8 + bsel + j;
                sRed[wid * 640 + b * 40 + cpos + 8 * ci] = part[ci][bsel + j];
            }
        __syncthreads();

        float sum = 0.f;
#pragma unroll
        for (int w = 0; w < 16; w++) sum += sRed[w * 640 + rbase];

        hv = tanhf(wxv + sum + bv);
        g_hbuf[1 - p][hoff] = hv;         // publish h
        y[ybase + ((long)s << 10)] = hv;  // y output
        __syncthreads();                  // CTA writes done before release
        if (tid == 0) {
            unsigned arrived = atom_add_release(&g_cnt, 1u) + 1u;
            unsigned step = (unsigned)(s + 1);
            if (arrived == step * (unsigned)NB_REC) st_release(&g_flag, step);
            while (ld_acquire(&g_flag) < step) {
            }
        }
        __syncthreads();
    }

    hlast[hoff] = hv;
}

// ---------------------------------------------------------------------------
extern "C" void kernel_launch(void* const* d_in, const int* in_sizes, int n_in,
                              void* d_out, int out_size) {
    const float* x = (const float*)d_in[0];      // [B,S,I]
    const float* h0 = (const float*)d_in[1];     // [B,H]
    const float* Wih_w = (const float*)d_in[2];  // [H,I]
    const float* Wih_b = (const float*)d_in[3];  // [H]
    const float* Whh_w = (const float*)d_in[4];  // [H,H]
    const float* Whh_b = (const float*)d_in[5];  // [H]
    float* y = (float*)d_out;                       // [B,S,H]
    float* hlast = y + (size_t)Bdim * Sdim * Hdim;  // [B,H]

    const int smem_bytes = (32 + 16) * 1028 * 4;  // 197376
    cudaFuncSetAttribute(rnn_recur, cudaFuncAttributeMaxDynamicSharedMemorySize,
                         smem_bytes);

    reset_state<<<1, 32>>>();
    copy_h<<<64, 256>>>(h0);
    wx_gemm<<<dim3(Hdim / 64, (Bdim * Sdim) / 128), 256>>>(x, Wih_w, Wih_b, y);
    rnn_recur<<<NB_REC, REC_THREADS, smem_bytes>>>(Whh_w, Whh_b, y, hlast);
}

// round 8
// speedup vs baseline: 1.4655x; 1.4655x over previous
#include <cuda_runtime.h>
#include <cuda_bf16.h>
#include <math.h>

#define Bdim 64
#define Sdim 1024
#define Idim 1024
#define Hdim 1024
#define NB_REC 128
#define REC_THREADS 512

// Scratch (allocation-free rule: __device__ globals)
__device__ float g_hbuf[2][Bdim * Hdim];
__device__ unsigned g_cnt;
__device__ unsigned g_flag;
// bf16 hi/lo split operands for tensor-core wx GEMM
__device__ __nv_bfloat16 g_Xhi[(size_t)Bdim * Sdim * Idim];
__device__ __nv_bfloat16 g_Xlo[(size_t)Bdim * Sdim * Idim];
__device__ __nv_bfloat16 g_Whi[Hdim * Idim];
__device__ __nv_bfloat16 g_Wlo[Hdim * Idim];

typedef unsigned long long ull;

// ---------------------------------------------------------------------------
__device__ __forceinline__ void fma2(ull& c, ull a, ull b) {
    asm("fma.rn.f32x2 %0, %1, %2, %0;" : "+l"(c) : "l"(a), "l"(b));
}
__device__ __forceinline__ float f2sum(ull v) {
    float2 f = *reinterpret_cast<float2*>(&v);
    return f.x + f.y;
}
__device__ __forceinline__ void cp16(void* d, const void* s) {
    unsigned sd = (unsigned)__cvta_generic_to_shared(d);
    asm volatile("cp.async.cg.shared.global [%0], [%1], 16;" :: "r"(sd), "l"(s));
}
#define CP_COMMIT() asm volatile("cp.async.commit_group;")
#define CP_WAIT(n) asm volatile("cp.async.wait_group %0;" :: "n"(n))

__device__ __forceinline__ void bulk_g2s(unsigned dst, const void* src,
                                         unsigned bytes, unsigned mbar) {
    asm volatile(
        "cp.async.bulk.shared::cluster.global.mbarrier::complete_tx::bytes "
        "[%0], [%1], %2, [%3];"
        :: "r"(dst), "l"(src), "r"(bytes), "r"(mbar) : "memory");
}
__device__ __forceinline__ void mbar_init(unsigned mbar, unsigned cnt) {
    asm volatile("mbarrier.init.shared.b64 [%0], %1;" :: "r"(mbar), "r"(cnt)
                 : "memory");
}
__device__ __forceinline__ void mbar_expect_tx(unsigned mbar, unsigned tx) {
    asm volatile("mbarrier.arrive.expect_tx.shared.b64 _, [%0], %1;"
                 :: "r"(mbar), "r"(tx) : "memory");
}
__device__ __forceinline__ void mbar_wait(unsigned mbar, unsigned parity) {
    asm volatile(
        "{\n\t"
        ".reg .pred P1;\n\t"
        "WAIT_LOOP_%=:\n\t"
        "mbarrier.try_wait.parity.acquire.cta.shared::cta.b64 P1, [%0], %1, 0x989680;\n\t"
        "@P1 bra.uni WAIT_DONE_%=;\n\t"
        "bra.uni WAIT_LOOP_%=;\n\t"
        "WAIT_DONE_%=:\n\t"
        "}"
        :: "r"(mbar), "r"(parity) : "memory");
}
__device__ __forceinline__ unsigned atom_add_release(unsigned* p, unsigned v) {
    unsigned old;
    asm volatile("atom.add.release.gpu.u32 %0, [%1], %2;"
                 : "=r"(old) : "l"(p), "r"(v) : "memory");
    return old;
}
__device__ __forceinline__ void st_release(unsigned* p, unsigned v) {
    asm volatile("st.release.gpu.u32 [%0], %1;" :: "l"(p), "r"(v) : "memory");
}
__device__ __forceinline__ unsigned ld_acquire(const unsigned* p) {
    unsigned v;
    asm volatile("ld.acquire.gpu.u32 %0, [%1];" : "=r"(v) : "l"(p) : "memory");
    return v;
}
// bf16 mma: D(16x8,f32) += A(16x16,row) * B(16x8,col)
__device__ __forceinline__ void mma_bf16(float* c, const unsigned* a,
                                         const unsigned* b) {
    asm volatile(
        "mma.sync.aligned.m16n8k16.row.col.f32.bf16.bf16.f32 "
        "{%0,%1,%2,%3}, {%4,%5,%6,%7}, {%8,%9}, {%0,%1,%2,%3};"
        : "+f"(c[0]), "+f"(c[1]), "+f"(c[2]), "+f"(c[3])
        : "r"(a[0]), "r"(a[1]), "r"(a[2]), "r"(a[3]), "r"(b[0]), "r"(b[1]));
}

// ---------------------------------------------------------------------------
__global__ void reset_state() {
    if (threadIdx.x == 0) {
        g_cnt = 0;
        g_flag = 0;
    }
}

__global__ void copy_h(const float* __restrict__ hin) {
    int i = blockIdx.x * blockDim.x + threadIdx.x;
    for (; i < Bdim * Hdim; i += gridDim.x * blockDim.x) g_hbuf[0][i] = hin[i];
}

// split fp32 -> bf16 hi + bf16 lo (lo = round(v - hi))
__global__ void split_x(const float* __restrict__ src) {
    size_t i = (size_t)(blockIdx.x * blockDim.x + threadIdx.x) * 4;
    const size_t n = (size_t)Bdim * Sdim * Idim;
    for (; i < n; i += (size_t)gridDim.x * blockDim.x * 4) {
        float4 v = *reinterpret_cast<const float4*>(src + i);
        __nv_bfloat16 h0 = __float2bfloat16(v.x), h1 = __float2bfloat16(v.y);
        __nv_bfloat16 h2 = __float2bfloat16(v.z), h3 = __float2bfloat16(v.w);
        __nv_bfloat162 hi01{h0, h1}, hi23{h2, h3};
        __nv_bfloat162 lo01{__float2bfloat16(v.x - __bfloat162float(h0)),
                            __float2bfloat16(v.y - __bfloat162float(h1))};
        __nv_bfloat162 lo23{__float2bfloat16(v.z - __bfloat162float(h2)),
                            __float2bfloat16(v.w - __bfloat162float(h3))};
        *reinterpret_cast<__nv_bfloat162*>(&g_Xhi[i]) = hi01;
        *reinterpret_cast<__nv_bfloat162*>(&g_Xhi[i + 2]) = hi23;
        *reinterpret_cast<__nv_bfloat162*>(&g_Xlo[i]) = lo01;
        *reinterpret_cast<__nv_bfloat162*>(&g_Xlo[i + 2]) = lo23;
    }
}

__global__ void split_w(const float* __restrict__ src) {
    int i = blockIdx.x * blockDim.x + threadIdx.x;
    for (; i < Hdim * Idim; i += gridDim.x * blockDim.x) {
        float v = src[i];
        __nv_bfloat16 h = __float2bfloat16(v);
        g_Whi[i] = h;
        g_Wlo[i] = __float2bfloat16(v - __bfloat162float(h));
    }
}

// ---------------------------------------------------------------------------
// Phase 1: wx = X @ Wih^T + b  via bf16 tensor cores, 2-way split, 3 products.
// CTA tile 128m x 64n, 8 warps (warp tile 32m x 32n = 2x4 mma tiles).
// k-chunk 32 (2 x k16 mma steps), cp.async double-buffered.
// Smem rows 40 bf16 (80B): fragment LDS.32 banks (20g+tg)%32 all distinct.
// ---------------------------------------------------------------------------
__global__ __launch_bounds__(256) void wx_gemm_tc(const float* __restrict__ bias,
                                                  float* __restrict__ out) {
    extern __shared__ __nv_bfloat16 smem_bf[];
    __nv_bfloat16* Ah = smem_bf;           // 2 bufs x 128 x 40
    __nv_bfloat16* Al = smem_bf + 10240;   // 2 bufs x 128 x 40
    __nv_bfloat16* Bh = smem_bf + 20480;   // 2 bufs x  64 x 40
    __nv_bfloat16* Bl = smem_bf + 25600;   // 2 bufs x  64 x 40

    const int tid = threadIdx.x;
    const int wid = tid >> 5, lane = tid & 31;
    const int g = lane >> 2, tg = lane & 3;
    const int warpM = (wid & 3) * 32;
    const int warpN = (wid >> 2) * 32;
    const long mBase = (long)blockIdx.y * 128;
    const int nBase = blockIdx.x * 64;

    const __nv_bfloat16* xh = g_Xhi + mBase * Idim;
    const __nv_bfloat16* xl = g_Xlo + mBase * Idim;
    const __nv_bfloat16* wh = g_Whi + (size_t)nBase * Idim;
    const __nv_bfloat16* wl = g_Wlo + (size_t)nBase * Idim;

    float acc[2][4][4];
#pragma unroll
    for (int i = 0; i < 2; i++)
#pragma unroll
        for (int j = 0; j < 4; j++)
#pragma unroll
            for (int r = 0; r < 4; r++) acc[i][j][r] = 0.f;

    // chunk loader: 6 cp16 per thread (A hi/lo: 2 each; B hi/lo: 1 each)
    const int ar0 = tid >> 2, aoff0 = (tid & 3) * 8;
    const int ar1 = (tid + 256) >> 2, aoff1 = ((tid + 256) & 3) * 8;
    const int br = tid >> 2, boff = (tid & 3) * 8;  // br 0..63

#define LOAD_CHUNK(B, K0)                                                      \
    do {                                                                       \
        cp16(&Ah[(B) * 5120 + ar0 * 40 + aoff0], xh + ar0 * Idim + (K0) + aoff0); \
        cp16(&Ah[(B) * 5120 + ar1 * 40 + aoff1], xh + ar1 * Idim + (K0) + aoff1); \
        cp16(&Al[(B) * 5120 + ar0 * 40 + aoff0], xl + ar0 * Idim + (K0) + aoff0); \
        cp16(&Al[(B) * 5120 + ar1 * 40 + aoff1], xl + ar1 * Idim + (K0) + aoff1); \
        cp16(&Bh[(B) * 2560 + br * 40 + boff], wh + br * Idim + (K0) + boff);  \
        cp16(&Bl[(B) * 2560 + br * 40 + boff], wl + br * Idim + (K0) + boff);  \
    } while (0)

    LOAD_CHUNK(0, 0);
    CP_COMMIT();

    int buf = 0;
    for (int kt = 0; kt < Idim / 32; kt++) {
        if (kt + 1 < Idim / 32) LOAD_CHUNK(buf ^ 1, (kt + 1) * 32);
        CP_COMMIT();
        CP_WAIT(1);
        __syncthreads();

        const __nv_bfloat16* ah = Ah + buf * 5120;
        const __nv_bfloat16* al = Al + buf * 5120;
        const __nv_bfloat16* bh = Bh + buf * 2560;
        const __nv_bfloat16* bl = Bl + buf * 2560;

#pragma unroll
        for (int kk = 0; kk < 32; kk += 16) {
            unsigned afh[2][4], afl[2][4], bfh[4][2], bfl[4][2];
#pragma unroll
            for (int i = 0; i < 2; i++) {
                int r0 = (warpM + i * 16 + g) * 40 + kk + tg * 2;
                int r1 = r0 + 8 * 40;
                afh[i][0] = *reinterpret_cast<const unsigned*>(&ah[r0]);
                afh[i][1] = *reinterpret_cast<const unsigned*>(&ah[r1]);
                afh[i][2] = *reinterpret_cast<const unsigned*>(&ah[r0 + 8]);
                afh[i][3] = *reinterpret_cast<const unsigned*>(&ah[r1 + 8]);
                afl[i][0] = *reinterpret_cast<const unsigned*>(&al[r0]);
                afl[i][1] = *reinterpret_cast<const unsigned*>(&al[r1]);
                afl[i][2] = *reinterpret_cast<const unsigned*>(&al[r0 + 8]);
                afl[i][3] = *reinterpret_cast<const unsigned*>(&al[r1 + 8]);
            }
#pragma unroll
            for (int j = 0; j < 4; j++) {
                int r0 = (warpN + j * 8 + g) * 40 + kk + tg * 2;
                bfh[j][0] = *reinterpret_cast<const unsigned*>(&bh[r0]);
                bfh[j][1] = *reinterpret_cast<const unsigned*>(&bh[r0 + 8]);
                bfl[j][0] = *reinterpret_cast<const unsigned*>(&bl[r0]);
                bfl[j][1] = *reinterpret_cast<const unsigned*>(&bl[r0 + 8]);
            }
#pragma unroll
            for (int i = 0; i < 2; i++)
#pragma unroll
                for (int j = 0; j < 4; j++) {
                    mma_bf16(acc[i][j], afh[i], bfh[j]);
                    mma_bf16(acc[i][j], afh[i], bfl[j]);
                    mma_bf16(acc[i][j], afl[i], bfh[j]);
                }
        }
        __syncthreads();
        buf ^= 1;
    }

    // epilogue: c0,c1 = (row, col..col+1); c2,c3 = (row+8, col..col+1)
#pragma unroll
    for (int i = 0; i < 2; i++) {
        long row = mBase + warpM + i * 16 + g;
#pragma unroll
        for (int j = 0; j < 4; j++) {
            int col = nBase + warpN + j * 8 + tg * 2;
            float b0 = bias[col], b1 = bias[col + 1];
            float2 v0{acc[i][j][0] + b0, acc[i][j][1] + b1};
            float2 v1{acc[i][j][2] + b0, acc[i][j][3] + b1};
            *reinterpret_cast<float2*>(&out[row * Hdim + col]) = v0;
            *reinterpret_cast<float2*>(&out[(row + 8) * Hdim + col]) = v1;
        }
    }
}

// ---------------------------------------------------------------------------
// Phase 2: persistent recurrence (R6 version — measured best).
// ---------------------------------------------------------------------------
__global__ __launch_bounds__(REC_THREADS, 1)
void rnn_recur(const float* __restrict__ Whh, const float* __restrict__ bhh,
               float* __restrict__ y, float* __restrict__ hlast) {
    extern __shared__ float sm[];
    float* sW = sm;                  // 32 x 1028
    float* sH = sm + 32 * 1028;      // 16 x 1028
    float* sRed = sH;                // overlay: 16 x 640 (after all sH reads)
    __shared__ unsigned long long mbar_storage;

    const int tid = threadIdx.x;
    const int bid = blockIdx.x;
    const int colBase = (bid & 31) * 32;
    const int batchBase = (bid >> 5) * 16;
    const unsigned mbar = (unsigned)__cvta_generic_to_shared(&mbar_storage);
    const unsigned sH_smem = (unsigned)__cvta_generic_to_shared(sH);

    if (tid == 0) mbar_init(mbar, 1);

#pragma unroll
    for (int i = 0; i < 16; i++) {
        int chunk = tid + i * REC_THREADS;
        int r = chunk >> 8, off = (chunk & 255) * 4;
        *reinterpret_cast<float4*>(&sW[r * 1028 + off]) =
            *reinterpret_cast<const float4*>(&Whh[(colBase + r) * Hdim + off]);
    }
    __syncthreads();  // mbar init + sW visible

    const int wid = tid >> 5, lane = tid & 31;
    const int cpos = lane & 7;
    const int bpos = lane >> 3;
    const int kBase = wid * 64;

    const int ob = tid >> 5;
    const int oc = tid & 31;
    const float bv = bhh[colBase + oc];
    const long ybase = (((long)(batchBase + ob)) << 20) + colBase + oc;
    const int hoff = ((batchBase + ob) << 10) + colBase + oc;
    const int rbase = ob * 40 + oc;
    float hv = 0.f;

    for (int s = 0; s < Sdim; s++) {
        const int p = s & 1;
        if (tid == 0) {
            asm volatile("fence.proxy.async.shared::cta;" ::: "memory");
            mbar_expect_tx(mbar, 16 * 4096);
            const float* hsrc = g_hbuf[p] + ((long)batchBase << 10);
#pragma unroll
            for (int r = 0; r < 16; r++) {
                bulk_g2s(sH_smem + (unsigned)(r * 1028 * 4), hsrc + (r << 10),
                         4096, mbar);
            }
        }
        float wxv = __ldg(&y[ybase + ((long)s << 10)]);
        mbar_wait(mbar, (unsigned)p);

        ull acc[4][4];
#pragma unroll
        for (int ci = 0; ci < 4; ci++)
#pragma unroll
            for (int bi = 0; bi < 4; bi++) acc[ci][bi] = 0ull;

#pragma unroll 4
        for (int q = 0; q < 16; q++) {
            const int k = kBase + q * 4;
            ulonglong2 wf[4], hf[4];
#pragma unroll
            for (int ci = 0; ci < 4; ci++)
                wf[ci] = *reinterpret_cast<const ulonglong2*>(
                    &sW[(cpos + 8 * ci) * 1028 + k]);
#pragma unroll
            for (int bi = 0; bi < 4; bi++)
                hf[bi] = *reinterpret_cast<const ulonglong2*>(
                    &sH[(bpos + 4 * bi) * 1028 + k]);
#pragma unroll
            for (int ci = 0; ci < 4; ci++)
#pragma unroll
                for (int bi = 0; bi < 4; bi++) fma2(acc[ci][bi], hf[bi].x, wf[ci].x);
#pragma unroll
            for (int ci = 0; ci < 4; ci++)
#pragma unroll
                for (int bi = 0; bi < 4; bi++) fma2(acc[ci][bi], hf[bi].y, wf[ci].y);
        }
        __syncthreads();

#pragma unroll
        for (int ci = 0; ci < 4; ci++)
#pragma unroll
            for (int bi = 0; bi < 4; bi++) {
                sRed[wid * 640 + (bpos + 4 * bi) * 40 + cpos + 8 * ci] =
                    f2sum(acc[ci][bi]);
            }
        __syncthreads();

        float sum = 0.f;
#pragma unroll
        for (int w = 0; w < 16; w++) sum += sRed[w * 640 + rbase];

        hv = tanhf(wxv + sum + bv);
        g_hbuf[1 - p][hoff] = hv;
        y[ybase + ((long)s << 10)] = hv;
        __syncthreads();
        if (tid == 0) {
            unsigned arrived = atom_add_release(&g_cnt, 1u) + 1u;
            unsigned step = (unsigned)(s + 1);
            if (arrived == step * (unsigned)NB_REC) st_release(&g_flag, step);
            while (ld_acquire(&g_flag) < step) {
            }
        }
        __syncthreads();
    }

    hlast[hoff] = hv;
}

// ---------------------------------------------------------------------------
extern "C" void kernel_launch(void* const* d_in, const int* in_sizes, int n_in,
                              void* d_out, int out_size) {
    const float* x = (const float*)d_in[0];      // [B,S,I]
    const float* h0 = (const float*)d_in[1];     // [B,H]
    const float* Wih_w = (const float*)d_in[2];  // [H,I]
    const float* Wih_b = (const float*)d_in[3];  // [H]
    const float* Whh_w = (const float*)d_in[4];  // [H,H]
    const float* Whh_b = (const float*)d_in[5];  // [H]
    float* y = (float*)d_out;                       // [B,S,H]
    float* hlast = y + (size_t)Bdim * Sdim * Hdim;  // [B,H]

    const int rec_smem = (32 + 16) * 1028 * 4;  // 197376
    cudaFuncSetAttribute(rnn_recur, cudaFuncAttributeMaxDynamicSharedMemorySize,
                         rec_smem);
    const int gemm_smem = 30720 * 2;  // 61440
    cudaFuncSetAttribute(wx_gemm_tc, cudaFuncAttributeMaxDynamicSharedMemorySize,
                         gemm_smem);

    reset_state<<<1, 32>>>();
    copy_h<<<64, 256>>>(h0);
    split_x<<<1024, 256>>>(x);
    split_w<<<256, 256>>>(Wih_w);
    wx_gemm_tc<<<dim3(Hdim / 64, (Bdim * Sdim) / 128), 256, gemm_smem>>>(Wih_b, y);
    rnn_recur<<<NB_REC, REC_THREADS, rec_smem>>>(Whh_w, Whh_b, y, hlast);
}